// round 8
// baseline (speedup 1.0000x reference)
#include <cuda_runtime.h>
#include <cuda_bf16.h>
#include <cstdint>
#include <cstddef>
#include <cstring>

// ----------------------------------------------------------------------------
// B=32, S=512, E=512, U=1024, G=4096.  out = (h, h, c) : 3*32*1024 f32
// Round-5 proven base; single change: coalesced LSTM partial store via smem.
// ----------------------------------------------------------------------------
#define NCTA 128

__device__ float          g_xw[(size_t)16384 * 4096];  // xW rows [t*32+b][4096]
__device__ float          g_part[4][32][4096];         // split-K partials
__device__ __nv_bfloat16  g_hh[2][32768];              // h hi, [b][u]
__device__ __nv_bfloat16  g_hl[2][32768];              // h lo
__device__ uint4          g_pkA_hi[524288];            // Ut packed A-fragments hi
__device__ uint4          g_pkA_lo[524288];            // Ut packed A-fragments lo
__device__ int            g_tokens[16384];             // [b*512+t]
__device__ unsigned       g_cnt;
__device__ volatile unsigned g_gen;

// ---------------- helpers ----------------
__device__ __forceinline__ int detect_is64(const int* raw, int thr, int* s_flag)
{
    if (thr == 0) *s_flag = 1;
    __syncthreads();
    if (thr < 128 && raw[2 * thr + 1] != 0) *s_flag = 0;
    __syncthreads();
    return *s_flag;
}
__device__ __forceinline__ unsigned short bf_hi(float f, float& rem) {
    __nv_bfloat16 b = __float2bfloat16(f);
    rem = f - __bfloat162float(b);
    unsigned short u; memcpy(&u, &b, 2); return u;
}
__device__ __forceinline__ unsigned short bf_of(float f) {
    __nv_bfloat16 b = __float2bfloat16(f);
    unsigned short u; memcpy(&u, &b, 2); return u;
}
__device__ __forceinline__ uint32_t smem_u32(const void* p) {
    uint32_t a;
    asm("{ .reg .u64 t; cvta.to.shared.u64 t, %1; cvt.u32.u64 %0, t; }" : "=r"(a) : "l"(p));
    return a;
}
#define LDSM4(r0, r1, r2, r3, addr) \
    asm volatile("ldmatrix.sync.aligned.m8n8.x4.shared.b16 {%0,%1,%2,%3}, [%4];" \
                 : "=r"(r0), "=r"(r1), "=r"(r2), "=r"(r3) : "r"(addr))
#define MMA_BF16(d, ax, ay, az, aw, b0, b1) \
    asm volatile("mma.sync.aligned.m16n8k16.row.col.f32.bf16.bf16.f32 " \
                 "{%0,%1,%2,%3}, {%4,%5,%6,%7}, {%8,%9}, {%0,%1,%2,%3};" \
                 : "+f"((d)[0]), "+f"((d)[1]), "+f"((d)[2]), "+f"((d)[3]) \
                 : "r"(ax), "r"(ay), "r"(az), "r"(aw), "r"(b0), "r"(b1))

// ----------------------------------------------------------------------------
// pack Ut into per-thread mma A-fragment order (round-5 verbatim, proven).
// ----------------------------------------------------------------------------
__global__ void __launch_bounds__(256) pack_U_kernel(const float* __restrict__ U)
{
    int idx = blockIdx.x * 256 + threadIdx.x;
    int t   = idx & 31;
    int c   = (idx >> 5) & 15;
    int w   = (idx >> 9) & 7;
    int cta = idx >> 12;
    int jb = cta >> 2, ks = cta & 3, u0 = jb << 5;
    int m0 = (w << 4) + (t >> 2), m1 = m0 + 8;
    int j0 = ((m0 >> 5) << 10) + u0 + (m0 & 31);
    int j1 = ((m1 >> 5) << 10) + u0 + (m1 & 31);
    int k0 = (ks << 8) + (c << 4) + ((t & 3) << 1);
    const float* U0 = U + (size_t)k0 * 4096;
    float f[4][2];
    f[0][0] = U0[j0];              f[0][1] = U0[4096 + j0];
    f[1][0] = U0[j1];              f[1][1] = U0[4096 + j1];
    f[2][0] = U0[8 * 4096 + j0];   f[2][1] = U0[9 * 4096 + j0];
    f[3][0] = U0[8 * 4096 + j1];   f[3][1] = U0[9 * 4096 + j1];
    uint32_t hi[4], lo[4];
#pragma unroll
    for (int r = 0; r < 4; ++r) {
        float rm0, rm1;
        unsigned short h0 = bf_hi(f[r][0], rm0), h1 = bf_hi(f[r][1], rm1);
        hi[r] = (uint32_t)h0 | ((uint32_t)h1 << 16);
        lo[r] = (uint32_t)bf_of(rm0) | ((uint32_t)bf_of(rm1) << 16);
    }
    g_pkA_hi[idx] = make_uint4(hi[0], hi[1], hi[2], hi[3]);
    g_pkA_lo[idx] = make_uint4(lo[0], lo[1], lo[2], lo[3]);
}

// ----------------------------------------------------------------------------
// Embed GEMM (round-5 FFMA version, proven): g_xw[r][n] = emb[tok(r)]@W + b
// ----------------------------------------------------------------------------
__global__ void __launch_bounds__(256) embed_gemm_kernel(
    const int*   __restrict__ raw,
    const float* __restrict__ emb,
    const float* __restrict__ W,
    const float* __restrict__ bias)
{
    __shared__ float As[2][16][132];
    __shared__ float Bs[2][16][128];
    __shared__ int s_is64;

    const int thr = threadIdx.x;
    const int is64 = detect_is64(raw, thr, &s_is64);
    const int n0 = blockIdx.x * 128;
    const int m0 = blockIdx.y * 128;
    const int tx = thr & 15;
    const int ty = thr >> 4;

    const float* aptr[2];
    int akq[2], am[2];
#pragma unroll
    for (int p = 0; p < 2; ++p) {
        int idx = p * 256 + thr;
        am[p]  = idx >> 2;
        akq[p] = idx & 3;
        int r  = m0 + am[p];
        int ti = (r & 31) * 512 + (r >> 5);
        int tok = is64 ? raw[2 * ti] : raw[ti];
        aptr[p] = emb + (size_t)tok * 512;
    }
    int bkk[2], bc4[2];
#pragma unroll
    for (int p = 0; p < 2; ++p) {
        int idx = p * 256 + thr;
        bkk[p] = idx >> 5;
        bc4[p] = idx & 31;
    }
#pragma unroll
    for (int p = 0; p < 2; ++p) {
        float4 v = *(const float4*)(aptr[p] + akq[p] * 4);
        As[0][akq[p] * 4 + 0][am[p]] = v.x;
        As[0][akq[p] * 4 + 1][am[p]] = v.y;
        As[0][akq[p] * 4 + 2][am[p]] = v.z;
        As[0][akq[p] * 4 + 3][am[p]] = v.w;
        float4 w4 = *(const float4*)(W + (size_t)bkk[p] * 4096 + n0 + bc4[p] * 4);
        *(float4*)&Bs[0][bkk[p]][bc4[p] * 4] = w4;
    }
    __syncthreads();

    float acc[8][8];
#pragma unroll
    for (int i = 0; i < 8; ++i)
#pragma unroll
        for (int j = 0; j < 8; ++j) acc[i][j] = 0.f;

    int buf = 0;
    for (int k0 = 0; k0 < 512; k0 += 16) {
        float4 an[2], bn[2];
        const bool more = (k0 + 16) < 512;
        if (more) {
#pragma unroll
            for (int p = 0; p < 2; ++p) {
                an[p] = *(const float4*)(aptr[p] + k0 + 16 + akq[p] * 4);
                bn[p] = *(const float4*)(W + (size_t)(k0 + 16 + bkk[p]) * 4096 + n0 + bc4[p] * 4);
            }
        }
#pragma unroll
        for (int kk = 0; kk < 16; ++kk) {
            float4 a0 = *(const float4*)&As[buf][kk][ty * 4];
            float4 a1 = *(const float4*)&As[buf][kk][64 + ty * 4];
            float4 b0 = *(const float4*)&Bs[buf][kk][tx * 4];
            float4 b1 = *(const float4*)&Bs[buf][kk][64 + tx * 4];
            float av[8] = {a0.x, a0.y, a0.z, a0.w, a1.x, a1.y, a1.z, a1.w};
            float bv[8] = {b0.x, b0.y, b0.z, b0.w, b1.x, b1.y, b1.z, b1.w};
#pragma unroll
            for (int i = 0; i < 8; ++i)
#pragma unroll
                for (int j = 0; j < 8; ++j)
                    acc[i][j] = fmaf(av[i], bv[j], acc[i][j]);
        }
        if (more) {
            int nb = buf ^ 1;
#pragma unroll
            for (int p = 0; p < 2; ++p) {
                As[nb][akq[p] * 4 + 0][am[p]] = an[p].x;
                As[nb][akq[p] * 4 + 1][am[p]] = an[p].y;
                As[nb][akq[p] * 4 + 2][am[p]] = an[p].z;
                As[nb][akq[p] * 4 + 3][am[p]] = an[p].w;
                *(float4*)&Bs[nb][bkk[p]][bc4[p] * 4] = bn[p];
            }
        }
        __syncthreads();
        buf ^= 1;
    }

    float4 bb0 = *(const float4*)(bias + n0 + tx * 4);
    float4 bb1 = *(const float4*)(bias + n0 + 64 + tx * 4);
#pragma unroll
    for (int i = 0; i < 8; ++i) {
        int m = (i < 4) ? (ty * 4 + i) : (64 + ty * 4 + i - 4);
        float* o = g_xw + (size_t)(m0 + m) * 4096 + n0;
        *(float4*)(o + tx * 4) = make_float4(acc[i][0] + bb0.x, acc[i][1] + bb0.y,
                                             acc[i][2] + bb0.z, acc[i][3] + bb0.w);
        *(float4*)(o + 64 + tx * 4) = make_float4(acc[i][4] + bb1.x, acc[i][5] + bb1.y,
                                                  acc[i][6] + bb1.z, acc[i][7] + bb1.w);
    }
}

// ---------------- grid barrier (round-5 verbatim, proven) ----------------
__device__ __forceinline__ void grid_barrier()
{
    __threadfence();
    __syncthreads();
    if (threadIdx.x == 0) {
        unsigned g = g_gen;
        if (atomicAdd(&g_cnt, 1u) == (NCTA - 1u)) {
            g_cnt = 0;
            __threadfence();
            g_gen = g + 1;
        } else {
            while (g_gen == g) { __nanosleep(32); }
        }
    }
    __syncthreads();
}

// ----------------------------------------------------------------------------
// LSTM scan: round-5 proven kernel; ONLY change = coalesced partial store
// through an smem transpose (aliases the consumed B-stage buffer).
// ----------------------------------------------------------------------------
__global__ void __launch_bounds__(256, 1) lstm_kernel(
    const int* __restrict__ raw, float* __restrict__ out)
{
    __shared__ __align__(16) char Bsm[2 * 16896];   // B-stage; zbuf aliases [0,16896)
    __shared__ int s_is64;

    const int thr  = threadIdx.x;
    const int lane = thr & 31;
    const int w    = thr >> 5;
    const int cta  = blockIdx.x;
    const int ks   = cta & 3;
    const int u0   = (cta >> 2) << 5;
    const int is64 = detect_is64(raw, thr, &s_is64);

    if (thr < 128) {
        int i = cta * 128 + thr;
        g_tokens[i] = is64 ? raw[2 * i] : raw[i];
    }
    const int tid = cta * 256 + thr;
    const int b_idx = tid >> 10, u_idx = tid & 1023;
    {
        unsigned short z = 0;
        *(unsigned short*)&g_hh[0][tid] = z;
        *(unsigned short*)&g_hl[0][tid] = z;
    }
    grid_barrier();

    float hreg = 0.f, creg = 0.f;
    float xwp[4];
    int tokv;
    {
        const float* xr = g_xw + (size_t)b_idx * 4096 + u_idx;
#pragma unroll
        for (int g = 0; g < 4; ++g) xwp[g] = __ldcs(xr + g * 1024);
        tokv = g_tokens[b_idx * 512];
    }

    const uint32_t sbB = smem_u32(Bsm);
    const int tile = lane >> 3, rsel = lane & 7;
    const int nrowoff = ((tile >> 1) & 1) * 8 + rsel;
    const int koff    = (tile & 1) * 16;
    const int abase   = (cta * 8 + w) * 512 + lane;
    const int m_r  = (w << 4) + (lane >> 2);
    const int m_r8 = m_r + 8;

    // coalesced partial-store mapping (NEW)
    const int cb   = thr >> 3;                       // b row 0..31
    const int coff = (thr & 7) << 4;                 // m offset 0,16,..,112
    const int cM   = ((coff >> 5) << 10) + u0 + (coff & 31);
    float* cdst    = &g_part[ks][cb][cM];
    float* zb      = (float*)Bsm;                    // [32 bcol][132] floats

    for (int t = 0; t < 512; ++t) {
        const __nv_bfloat16* hsrc0 = g_hh[t & 1] + ks * 256;
        const __nv_bfloat16* hsrc1 = g_hl[t & 1] + ks * 256;
#pragma unroll
        for (int ii = 0; ii < 8; ++ii) {
            int idx  = ii * 256 + thr;
            int hsel = idx >> 10;
            int rq   = idx & 1023;
            int row  = rq >> 5, q = rq & 31;
            const __nv_bfloat16* src = (hsel ? hsrc1 : hsrc0) + row * 1024;
            uint4 v = __ldcg((const uint4*)src + q);
            *(uint4*)(Bsm + hsel * 16896 + row * 528 + q * 16) = v;
        }
        __syncthreads();

        float d[4][4];
#pragma unroll
        for (int nf = 0; nf < 4; ++nf)
#pragma unroll
            for (int i = 0; i < 4; ++i) d[nf][i] = 0.f;

#pragma unroll 4
        for (int c = 0; c < 16; ++c) {
            uint4 ah = __ldg(&g_pkA_hi[abase + c * 32]);
            uint4 al = __ldg(&g_pkA_lo[abase + c * 32]);
            uint32_t bh[8], bl[8];
            uint32_t a0 = sbB + (0 + nrowoff) * 528 + c * 32 + koff;
            uint32_t a1 = sbB + (16 + nrowoff) * 528 + c * 32 + koff;
            LDSM4(bh[0], bh[1], bh[2], bh[3], a0);
            LDSM4(bh[4], bh[5], bh[6], bh[7], a1);
            LDSM4(bl[0], bl[1], bl[2], bl[3], a0 + 16896);
            LDSM4(bl[4], bl[5], bl[6], bl[7], a1 + 16896);
#pragma unroll
            for (int nf = 0; nf < 4; ++nf) {
                MMA_BF16(d[nf], ah.x, ah.y, ah.z, ah.w, bh[nf * 2], bh[nf * 2 + 1]);
                MMA_BF16(d[nf], ah.x, ah.y, ah.z, ah.w, bl[nf * 2], bl[nf * 2 + 1]);
                MMA_BF16(d[nf], al.x, al.y, al.z, al.w, bh[nf * 2], bh[nf * 2 + 1]);
            }
        }

        // ---- NEW: transpose d-frags through smem, then coalesced store ----
        __syncthreads();                     // all warps done reading Bsm
#pragma unroll
        for (int nf = 0; nf < 4; ++nf) {
            int bcol = nf * 8 + ((lane & 3) << 1);
            zb[bcol * 132 + m_r]        = d[nf][0];
            zb[(bcol + 1) * 132 + m_r]  = d[nf][1];
            zb[bcol * 132 + m_r8]       = d[nf][2];
            zb[(bcol + 1) * 132 + m_r8] = d[nf][3];
        }
        __syncthreads();
        {
            const float* src = zb + cb * 132 + coff;
            float4 v0 = *(const float4*)(src);
            float4 v1 = *(const float4*)(src + 4);
            float4 v2 = *(const float4*)(src + 8);
            float4 v3 = *(const float4*)(src + 12);
            *(float4*)(cdst)      = v0;
            *(float4*)(cdst + 4)  = v1;
            *(float4*)(cdst + 8)  = v2;
            *(float4*)(cdst + 12) = v3;
        }
        grid_barrier();

        {
            float z0 = xwp[0], z1 = xwp[1], z2 = xwp[2], z3 = xwp[3];
#pragma unroll
            for (int kr = 0; kr < 4; ++kr) {
                z0 += __ldcg(&g_part[kr][b_idx][u_idx]);
                z1 += __ldcg(&g_part[kr][b_idx][u_idx + 1024]);
                z2 += __ldcg(&g_part[kr][b_idx][u_idx + 2048]);
                z3 += __ldcg(&g_part[kr][b_idx][u_idx + 3072]);
            }
            float gi = tanhf(z0);
            float gf = tanhf(z1);
            float gg = tanhf(z2);
            float go = tanhf(z3);
            float cn = fmaf(gf, creg, gi * gg);
            float hn = go * tanhf(cn);
            if (tokv != 0) { creg = cn; hreg = hn; }
            float rem;
            unsigned short hb = bf_hi(hreg, rem);
            *(unsigned short*)&g_hh[(t + 1) & 1][tid] = hb;
            *(unsigned short*)&g_hl[(t + 1) & 1][tid] = bf_of(rem);

            if (t + 1 < 512) {
                const float* xr = g_xw + ((size_t)(t + 1) * 32 + b_idx) * 4096 + u_idx;
#pragma unroll
                for (int g = 0; g < 4; ++g) xwp[g] = __ldcs(xr + g * 1024);
                tokv = g_tokens[b_idx * 512 + t + 1];
            }
        }
        grid_barrier();
    }

    out[b_idx * 1024 + u_idx]         = hreg;
    out[32768 + b_idx * 1024 + u_idx] = hreg;
    out[65536 + b_idx * 1024 + u_idx] = creg;
}

// ---------------- launch ----------------
extern "C" void kernel_launch(void* const* d_in, const int* in_sizes, int n_in,
                              void* d_out, int out_size)
{
    const int*   tokens_raw = (const int*)  d_in[0];
    const float* emb        = (const float*)d_in[1];
    const float* W          = (const float*)d_in[2];
    const float* U          = (const float*)d_in[3];
    const float* bias       = (const float*)d_in[4];
    float*       out        = (float*)d_out;
    (void)in_sizes; (void)n_in; (void)out_size;

    pack_U_kernel<<<2048, 256>>>(U);
    embed_gemm_kernel<<<dim3(32, 128), 256>>>(tokens_raw, emb, W, bias);
    lstm_kernel<<<NCTA, 256>>>(tokens_raw, out);
}

// round 9
// speedup vs baseline: 1.1590x; 1.1590x over previous
#include <cuda_runtime.h>
#include <cuda_bf16.h>
#include <cstdint>
#include <cstddef>
#include <cstring>

// ----------------------------------------------------------------------------
// B=32, S=512, E=512, U=1024, G=4096.  out = (h, h, c) : 3*32*1024 f32
// Single persistent kernel: z_t = [h_t ; x_t] @ [U ; W] + bias, fused.
// K = 1536 (1024 h + 512 x), split-K over 4 CTAs-groups, bf16x3 mma.sync.
// ----------------------------------------------------------------------------
#define NCTA 128

__device__ float          g_part[4][32][4096];         // split-K partials
__device__ __nv_bfloat16  g_hh[2][32768];              // h hi, [b][u]
__device__ __nv_bfloat16  g_hl[2][32768];              // h lo
__device__ uint4          g_pkA_hi[786432];            // [U;W] packed A-frags hi
__device__ uint4          g_pkA_lo[786432];            // [U;W] packed A-frags lo
__device__ int            g_tokens[16384];             // [b*512+t]
__device__ unsigned       g_cnt;
__device__ volatile unsigned g_gen;

// smem layout (dynamic, 51200 B):
//   [0      , 16896) : B-h hi   (32 rows x 528 B pitch, 512 B data)
//   [16896  , 33792) : B-h lo
//   [33792  , 42496) : B-x hi   (32 rows x 272 B pitch, 256 B data)
//   [42496  , 51200) : B-x lo
#define SM_XOFF  33792
#define SM_XHALF 8704
#define SM_TOTAL 51200

// ---------------- helpers ----------------
__device__ __forceinline__ int detect_is64(const int* raw, int thr, int* s_flag)
{
    if (thr == 0) *s_flag = 1;
    __syncthreads();
    if (thr < 128 && raw[2 * thr + 1] != 0) *s_flag = 0;
    __syncthreads();
    return *s_flag;
}
__device__ __forceinline__ unsigned short bf_hi(float f, float& rem) {
    __nv_bfloat16 b = __float2bfloat16(f);
    rem = f - __bfloat162float(b);
    unsigned short u; memcpy(&u, &b, 2); return u;
}
__device__ __forceinline__ unsigned short bf_of(float f) {
    __nv_bfloat16 b = __float2bfloat16(f);
    unsigned short u; memcpy(&u, &b, 2); return u;
}
__device__ __forceinline__ uint32_t smem_u32(const void* p) {
    uint32_t a;
    asm("{ .reg .u64 t; cvta.to.shared.u64 t, %1; cvt.u32.u64 %0, t; }" : "=r"(a) : "l"(p));
    return a;
}
#define LDSM4(r0, r1, r2, r3, addr) \
    asm volatile("ldmatrix.sync.aligned.m8n8.x4.shared.b16 {%0,%1,%2,%3}, [%4];" \
                 : "=r"(r0), "=r"(r1), "=r"(r2), "=r"(r3) : "r"(addr))
#define MMA_BF16(d, ax, ay, az, aw, b0, b1) \
    asm volatile("mma.sync.aligned.m16n8k16.row.col.f32.bf16.bf16.f32 " \
                 "{%0,%1,%2,%3}, {%4,%5,%6,%7}, {%8,%9}, {%0,%1,%2,%3};" \
                 : "+f"((d)[0]), "+f"((d)[1]), "+f"((d)[2]), "+f"((d)[3]) \
                 : "r"(ax), "r"(ay), "r"(az), "r"(aw), "r"(b0), "r"(b1))

// ----------------------------------------------------------------------------
// pack [U;W] into per-thread mma A-fragment order.
// slot = ((cta*8 + w)*24 + c)*32 + lane.
// chunks 0..15: U rows, k = ks*256 + c*16 + ...   (proven pack_U math)
// chunks 16..23: W rows, k' = ks*128 + (c-16)*16 + ...  (same math, W source)
// A[m][k] = src[k][j(m)], j(m) = (m>>5)*1024 + u0 + (m&31).
// ----------------------------------------------------------------------------
__global__ void __launch_bounds__(256) pack_UW_kernel(
    const float* __restrict__ U, const float* __restrict__ W)
{
    int idx  = blockIdx.x * 256 + threadIdx.x;        // 0..786431
    int lane = idx & 31;
    int tmp  = idx >> 5;
    int c    = tmp % 24;
    int tmp2 = tmp / 24;
    int w    = tmp2 & 7;
    int cta  = tmp2 >> 3;
    int jb = cta >> 2, ks = cta & 3, u0 = jb << 5;
    int m0 = (w << 4) + (lane >> 2), m1 = m0 + 8;
    int j0 = ((m0 >> 5) << 10) + u0 + (m0 & 31);
    int j1 = ((m1 >> 5) << 10) + u0 + (m1 & 31);

    const float* base;
    if (c < 16) base = U + (size_t)((ks << 8) + (c << 4) + ((lane & 3) << 1)) * 4096;
    else        base = W + (size_t)((ks << 7) + ((c - 16) << 4) + ((lane & 3) << 1)) * 4096;

    float f[4][2];
    f[0][0] = base[j0];              f[0][1] = base[4096 + j0];
    f[1][0] = base[j1];              f[1][1] = base[4096 + j1];
    f[2][0] = base[8 * 4096 + j0];   f[2][1] = base[9 * 4096 + j0];
    f[3][0] = base[8 * 4096 + j1];   f[3][1] = base[9 * 4096 + j1];
    uint32_t hi[4], lo[4];
#pragma unroll
    for (int r = 0; r < 4; ++r) {
        float rm0, rm1;
        unsigned short h0 = bf_hi(f[r][0], rm0), h1 = bf_hi(f[r][1], rm1);
        hi[r] = (uint32_t)h0 | ((uint32_t)h1 << 16);
        lo[r] = (uint32_t)bf_of(rm0) | ((uint32_t)bf_of(rm1) << 16);
    }
    g_pkA_hi[idx] = make_uint4(hi[0], hi[1], hi[2], hi[3]);
    g_pkA_lo[idx] = make_uint4(lo[0], lo[1], lo[2], lo[3]);
}

// ---------------- grid barrier (proven) ----------------
__device__ __forceinline__ void grid_barrier()
{
    __threadfence();
    __syncthreads();
    if (threadIdx.x == 0) {
        unsigned g = g_gen;
        if (atomicAdd(&g_cnt, 1u) == (NCTA - 1u)) {
            g_cnt = 0;
            __threadfence();
            g_gen = g + 1;
        } else {
            while (g_gen == g) { __nanosleep(32); }
        }
    }
    __syncthreads();
}

// ----------------------------------------------------------------------------
// Fused LSTM scan: 128 CTAs, 256 thr.  cta = jb*4 + ks.
// Phase 1: part[ks][b][M] = sum over h-k [ks*256,+256) and x-k [ks*128,+128)
//   of [h;x] fragments vs packed [U;W].  24 chunks of K16, bf16x3.
// Phase 2: thread (b,u): z = bias + sum_ks partials; gates; mask; h hi/lo.
// ----------------------------------------------------------------------------
__global__ void __launch_bounds__(256, 1) lstm_kernel(
    const int*   __restrict__ raw,
    const float* __restrict__ emb,
    const float* __restrict__ bias,
    float*       __restrict__ out)
{
    extern __shared__ __align__(16) char sm[];
    __shared__ int s_is64;

    const int thr  = threadIdx.x;
    const int lane = thr & 31;
    const int w    = thr >> 5;
    const int cta  = blockIdx.x;
    const int ks   = cta & 3;
    const int u0   = (cta >> 2) << 5;
    const int is64 = detect_is64(raw, thr, &s_is64);

    if (thr < 128) {
        int i = cta * 128 + thr;
        g_tokens[i] = is64 ? raw[2 * i] : raw[i];
    }
    const int tid = cta * 256 + thr;
    const int b_idx = tid >> 10, u_idx = tid & 1023;
    {
        unsigned short z = 0;
        *(unsigned short*)&g_hh[0][tid] = z;
        *(unsigned short*)&g_hl[0][tid] = z;
    }
    grid_barrier();

    float hreg = 0.f, creg = 0.f;
    float biasr[4];
#pragma unroll
    for (int g = 0; g < 4; ++g) biasr[g] = bias[g * 1024 + u_idx];
    int tokv = g_tokens[b_idx * 512];

    // mma geometry (proven)
    const uint32_t sbB = smem_u32(sm);
    const uint32_t sbX = sbB + SM_XOFF;
    const int tile = lane >> 3, rsel = lane & 7;
    const int nrowoff = ((tile >> 1) & 1) * 8 + rsel;
    const int koff    = (tile & 1) * 16;
    const int abase   = (cta * 8 + w) * 768 + lane;    // 24 chunks * 32 lanes
    const int m_r  = (w << 4) + (lane >> 2);
    const int Mg0  = ((m_r >> 5) << 10) + u0 + (m_r & 31);
    const int m_r8 = m_r + 8;
    const int Mg8  = ((m_r8 >> 5) << 10) + u0 + (m_r8 & 31);

    // x staging mapping
    const int xrow = thr >> 3;             // 0..31  (batch row)
    const int xq   = thr & 7;              // 16 floats each

    for (int t = 0; t < 512; ++t) {
        // ---- stage B-h: h slice [32][256] hi+lo (proven layout) ----
        const __nv_bfloat16* hsrc0 = g_hh[t & 1] + ks * 256;
        const __nv_bfloat16* hsrc1 = g_hl[t & 1] + ks * 256;
#pragma unroll
        for (int ii = 0; ii < 8; ++ii) {
            int idx  = ii * 256 + thr;
            int hsel = idx >> 10;
            int rq   = idx & 1023;
            int row  = rq >> 5, q = rq & 31;
            const __nv_bfloat16* src = (hsel ? hsrc1 : hsrc0) + row * 1024;
            uint4 v = __ldcg((const uint4*)src + q);
            *(uint4*)(sm + hsel * 16896 + row * 528 + q * 16) = v;
        }
        // ---- stage B-x: emb gather [32][128] fp32 -> hi/lo bf16 ----
        {
            int tokx = g_tokens[xrow * 512 + t];
            const float* xs = emb + (size_t)tokx * 512 + ks * 128 + xq * 16;
            uint32_t hiw[8], low[8];
#pragma unroll
            for (int p = 0; p < 4; ++p) {
                float4 v = __ldg((const float4*)(xs + p * 4));
                float r0, r1, r2, r3;
                unsigned short h0 = bf_hi(v.x, r0), h1 = bf_hi(v.y, r1);
                unsigned short h2 = bf_hi(v.z, r2), h3 = bf_hi(v.w, r3);
                hiw[p * 2]     = (uint32_t)h0 | ((uint32_t)h1 << 16);
                hiw[p * 2 + 1] = (uint32_t)h2 | ((uint32_t)h3 << 16);
                low[p * 2]     = (uint32_t)bf_of(r0) | ((uint32_t)bf_of(r1) << 16);
                low[p * 2 + 1] = (uint32_t)bf_of(r2) | ((uint32_t)bf_of(r3) << 16);
            }
            char* xd = sm + SM_XOFF + xrow * 272 + xq * 32;
            *(uint4*)xd        = make_uint4(hiw[0], hiw[1], hiw[2], hiw[3]);
            *(uint4*)(xd + 16) = make_uint4(hiw[4], hiw[5], hiw[6], hiw[7]);
            *(uint4*)(xd + SM_XHALF)      = make_uint4(low[0], low[1], low[2], low[3]);
            *(uint4*)(xd + SM_XHALF + 16) = make_uint4(low[4], low[5], low[6], low[7]);
        }
        __syncthreads();

        // ---- mma mainloop: 24 k-chunks (16 h + 8 x) ----
        float d[4][4];
#pragma unroll
        for (int nf = 0; nf < 4; ++nf)
#pragma unroll
            for (int i = 0; i < 4; ++i) d[nf][i] = 0.f;

#pragma unroll 4
        for (int c = 0; c < 24; ++c) {
            uint4 ah = __ldg(&g_pkA_hi[abase + c * 32]);
            uint4 al = __ldg(&g_pkA_lo[abase + c * 32]);
            uint32_t a0, a1, loOff;
            if (c < 16) {
                a0 = sbB + nrowoff * 528 + c * 32 + koff;
                a1 = a0 + 16 * 528;
                loOff = 16896;
            } else {
                a0 = sbX + nrowoff * 272 + (c - 16) * 32 + koff;
                a1 = a0 + 16 * 272;
                loOff = SM_XHALF;
            }
            uint32_t bh[8], bl[8];
            LDSM4(bh[0], bh[1], bh[2], bh[3], a0);
            LDSM4(bh[4], bh[5], bh[6], bh[7], a1);
            LDSM4(bl[0], bl[1], bl[2], bl[3], a0 + loOff);
            LDSM4(bl[4], bl[5], bl[6], bl[7], a1 + loOff);
#pragma unroll
            for (int nf = 0; nf < 4; ++nf) {
                MMA_BF16(d[nf], ah.x, ah.y, ah.z, ah.w, bh[nf * 2], bh[nf * 2 + 1]);
                MMA_BF16(d[nf], ah.x, ah.y, ah.z, ah.w, bl[nf * 2], bl[nf * 2 + 1]);
                MMA_BF16(d[nf], al.x, al.y, al.z, al.w, bh[nf * 2], bh[nf * 2 + 1]);
            }
        }

        // ---- store partials (round-5 proven scattered stores) ----
#pragma unroll
        for (int nf = 0; nf < 4; ++nf) {
            int bcol = nf * 8 + ((lane & 3) << 1);
            g_part[ks][bcol][Mg0]     = d[nf][0];
            g_part[ks][bcol + 1][Mg0] = d[nf][1];
            g_part[ks][bcol][Mg8]     = d[nf][2];
            g_part[ks][bcol + 1][Mg8] = d[nf][3];
        }
        grid_barrier();

        // ---- phase 2: reduce + gates ----
        {
            float z0 = biasr[0], z1 = biasr[1], z2 = biasr[2], z3 = biasr[3];
#pragma unroll
            for (int kr = 0; kr < 4; ++kr) {
                z0 += __ldcg(&g_part[kr][b_idx][u_idx]);
                z1 += __ldcg(&g_part[kr][b_idx][u_idx + 1024]);
                z2 += __ldcg(&g_part[kr][b_idx][u_idx + 2048]);
                z3 += __ldcg(&g_part[kr][b_idx][u_idx + 3072]);
            }
            float gi = tanhf(z0);
            float gf = tanhf(z1);
            float gg = tanhf(z2);
            float go = tanhf(z3);
            float cn = fmaf(gf, creg, gi * gg);
            float hn = go * tanhf(cn);
            if (tokv != 0) { creg = cn; hreg = hn; }
            float rem;
            unsigned short hb = bf_hi(hreg, rem);
            *(unsigned short*)&g_hh[(t + 1) & 1][tid] = hb;
            *(unsigned short*)&g_hl[(t + 1) & 1][tid] = bf_of(rem);

            if (t + 1 < 512) tokv = g_tokens[b_idx * 512 + t + 1];
        }
        grid_barrier();
    }

    out[b_idx * 1024 + u_idx]         = hreg;
    out[32768 + b_idx * 1024 + u_idx] = hreg;
    out[65536 + b_idx * 1024 + u_idx] = creg;
}

// ---------------- launch ----------------
extern "C" void kernel_launch(void* const* d_in, const int* in_sizes, int n_in,
                              void* d_out, int out_size)
{
    const int*   tokens_raw = (const int*)  d_in[0];
    const float* emb        = (const float*)d_in[1];
    const float* W          = (const float*)d_in[2];
    const float* U          = (const float*)d_in[3];
    const float* bias       = (const float*)d_in[4];
    float*       out        = (float*)d_out;
    (void)in_sizes; (void)n_in; (void)out_size;

    cudaFuncSetAttribute(lstm_kernel,
                         cudaFuncAttributeMaxDynamicSharedMemorySize, SM_TOTAL);

    pack_UW_kernel<<<3072, 256>>>(U, W);
    lstm_kernel<<<NCTA, 256, SM_TOTAL>>>(tokens_raw, emb, bias, out);
}

// round 10
// speedup vs baseline: 1.2794x; 1.1038x over previous
#include <cuda_runtime.h>
#include <cuda_bf16.h>
#include <cstdint>
#include <cstddef>
#include <cstring>

// ----------------------------------------------------------------------------
// B=32, S=512, E=512, U=1024, G=4096.  out = (h, h, c) : 3*32*1024 f32
// Single persistent kernel: z_t = [h_t ; x_t] @ [U ; W] + bias, fused.
// K = 1536 (1024 h + 512 x), split-K over 4 CTA-groups, bf16x3 mma.sync.
// Round-10 change (only): A-lo cached in smem, A-hi L1-partitioned + prefetch.
// ----------------------------------------------------------------------------
#define NCTA 128

__device__ float          g_part[4][32][4096];         // split-K partials
__device__ __nv_bfloat16  g_hh[2][32768];              // h hi, [b][u]
__device__ __nv_bfloat16  g_hl[2][32768];              // h lo
__device__ uint4          g_pkA_hi[786432];            // [U;W] packed A-frags hi
__device__ uint4          g_pkA_lo[786432];            // [U;W] packed A-frags lo
__device__ int            g_tokens[16384];             // [b*512+t]
__device__ unsigned       g_cnt;
__device__ volatile unsigned g_gen;

// smem layout (dynamic, 149504 B):
//   [0      , 16896) : B-h hi   (32 rows x 528 B pitch, 512 B data)
//   [16896  , 33792) : B-h lo
//   [33792  , 42496) : B-x hi   (32 rows x 272 B pitch, 256 B data)
//   [42496  , 51200) : B-x lo
//   [51200  ,149504) : A-lo frags (8 warps x 24 chunks x 32 lanes x 16 B)
#define SM_XOFF  33792
#define SM_XHALF 8704
#define SM_ALO   51200
#define SM_TOTAL 149504

// ---------------- helpers ----------------
__device__ __forceinline__ int detect_is64(const int* raw, int thr, int* s_flag)
{
    if (thr == 0) *s_flag = 1;
    __syncthreads();
    if (thr < 128 && raw[2 * thr + 1] != 0) *s_flag = 0;
    __syncthreads();
    return *s_flag;
}
__device__ __forceinline__ unsigned short bf_hi(float f, float& rem) {
    __nv_bfloat16 b = __float2bfloat16(f);
    rem = f - __bfloat162float(b);
    unsigned short u; memcpy(&u, &b, 2); return u;
}
__device__ __forceinline__ unsigned short bf_of(float f) {
    __nv_bfloat16 b = __float2bfloat16(f);
    unsigned short u; memcpy(&u, &b, 2); return u;
}
__device__ __forceinline__ uint32_t smem_u32(const void* p) {
    uint32_t a;
    asm("{ .reg .u64 t; cvta.to.shared.u64 t, %1; cvt.u32.u64 %0, t; }" : "=r"(a) : "l"(p));
    return a;
}
__device__ __forceinline__ uint4 ldcg4(const uint4* p) {
    uint4 v;
    asm volatile("ld.global.cg.v4.u32 {%0,%1,%2,%3}, [%4];"
                 : "=r"(v.x), "=r"(v.y), "=r"(v.z), "=r"(v.w) : "l"(p));
    return v;
}
#define LDSM4(r0, r1, r2, r3, addr) \
    asm volatile("ldmatrix.sync.aligned.m8n8.x4.shared.b16 {%0,%1,%2,%3}, [%4];" \
                 : "=r"(r0), "=r"(r1), "=r"(r2), "=r"(r3) : "r"(addr))
#define MMA_BF16(d, ax, ay, az, aw, b0, b1) \
    asm volatile("mma.sync.aligned.m16n8k16.row.col.f32.bf16.bf16.f32 " \
                 "{%0,%1,%2,%3}, {%4,%5,%6,%7}, {%8,%9}, {%0,%1,%2,%3};" \
                 : "+f"((d)[0]), "+f"((d)[1]), "+f"((d)[2]), "+f"((d)[3]) \
                 : "r"(ax), "r"(ay), "r"(az), "r"(aw), "r"(b0), "r"(b1))

// ----------------------------------------------------------------------------
// pack [U;W] into per-thread mma A-fragment order (round-9 verbatim, proven).
// ----------------------------------------------------------------------------
__global__ void __launch_bounds__(256) pack_UW_kernel(
    const float* __restrict__ U, const float* __restrict__ W)
{
    int idx  = blockIdx.x * 256 + threadIdx.x;        // 0..786431
    int lane = idx & 31;
    int tmp  = idx >> 5;
    int c    = tmp % 24;
    int tmp2 = tmp / 24;
    int w    = tmp2 & 7;
    int cta  = tmp2 >> 3;
    int jb = cta >> 2, ks = cta & 3, u0 = jb << 5;
    int m0 = (w << 4) + (lane >> 2), m1 = m0 + 8;
    int j0 = ((m0 >> 5) << 10) + u0 + (m0 & 31);
    int j1 = ((m1 >> 5) << 10) + u0 + (m1 & 31);

    const float* base;
    if (c < 16) base = U + (size_t)((ks << 8) + (c << 4) + ((lane & 3) << 1)) * 4096;
    else        base = W + (size_t)((ks << 7) + ((c - 16) << 4) + ((lane & 3) << 1)) * 4096;

    float f[4][2];
    f[0][0] = base[j0];              f[0][1] = base[4096 + j0];
    f[1][0] = base[j1];              f[1][1] = base[4096 + j1];
    f[2][0] = base[8 * 4096 + j0];   f[2][1] = base[9 * 4096 + j0];
    f[3][0] = base[8 * 4096 + j1];   f[3][1] = base[9 * 4096 + j1];
    uint32_t hi[4], lo[4];
#pragma unroll
    for (int r = 0; r < 4; ++r) {
        float rm0, rm1;
        unsigned short h0 = bf_hi(f[r][0], rm0), h1 = bf_hi(f[r][1], rm1);
        hi[r] = (uint32_t)h0 | ((uint32_t)h1 << 16);
        lo[r] = (uint32_t)bf_of(rm0) | ((uint32_t)bf_of(rm1) << 16);
    }
    g_pkA_hi[idx] = make_uint4(hi[0], hi[1], hi[2], hi[3]);
    g_pkA_lo[idx] = make_uint4(lo[0], lo[1], lo[2], lo[3]);
}

// ---------------- grid barrier (proven) ----------------
__device__ __forceinline__ void grid_barrier()
{
    __threadfence();
    __syncthreads();
    if (threadIdx.x == 0) {
        unsigned g = g_gen;
        if (atomicAdd(&g_cnt, 1u) == (NCTA - 1u)) {
            g_cnt = 0;
            __threadfence();
            g_gen = g + 1;
        } else {
            while (g_gen == g) { __nanosleep(32); }
        }
    }
    __syncthreads();
}

// ----------------------------------------------------------------------------
// Fused LSTM scan: 128 CTAs, 256 thr.  cta = jb*4 + ks.
// ----------------------------------------------------------------------------
__global__ void __launch_bounds__(256, 1) lstm_kernel(
    const int*   __restrict__ raw,
    const float* __restrict__ emb,
    const float* __restrict__ bias,
    float*       __restrict__ out)
{
    extern __shared__ __align__(16) char sm[];
    __shared__ int s_is64;

    const int thr  = threadIdx.x;
    const int lane = thr & 31;
    const int w    = thr >> 5;
    const int cta  = blockIdx.x;
    const int ks   = cta & 3;
    const int u0   = (cta >> 2) << 5;
    const int is64 = detect_is64(raw, thr, &s_is64);

    if (thr < 128) {
        int i = cta * 128 + thr;
        g_tokens[i] = is64 ? raw[2 * i] : raw[i];
    }
    const int tid = cta * 256 + thr;
    const int b_idx = tid >> 10, u_idx = tid & 1023;
    {
        unsigned short z = 0;
        *(unsigned short*)&g_hh[0][tid] = z;
        *(unsigned short*)&g_hl[0][tid] = z;
    }

    // mma geometry (proven)
    const uint32_t sbB = smem_u32(sm);
    const uint32_t sbX = sbB + SM_XOFF;
    const int tile = lane >> 3, rsel = lane & 7;
    const int nrowoff = ((tile >> 1) & 1) * 8 + rsel;
    const int koff    = (tile & 1) * 16;
    const int abase   = (cta * 8 + w) * 768 + lane;    // 24 chunks * 32 lanes
    const int m_r  = (w << 4) + (lane >> 2);
    const int Mg0  = ((m_r >> 5) << 10) + u0 + (m_r & 31);
    const int m_r8 = m_r + 8;
    const int Mg8  = ((m_r8 >> 5) << 10) + u0 + (m_r8 & 31);

    // NEW: copy this thread's 24 A-lo fragments into smem (private slots,
    // written and read by the same thread -> no sync needed).
    char* aloPtr = sm + SM_ALO + (size_t)(w * 768 + lane) * 16;
    {
        const uint4* src = g_pkA_lo + abase;
#pragma unroll
        for (int c = 0; c < 24; ++c)
            *(uint4*)(aloPtr + c * 512) = __ldg(src + c * 32);
    }
    grid_barrier();

    float hreg = 0.f, creg = 0.f;
    float biasr[4];
#pragma unroll
    for (int g = 0; g < 4; ++g) biasr[g] = bias[g * 1024 + u_idx];
    int tokv = g_tokens[b_idx * 512];

    // x staging mapping
    const int xrow = thr >> 3;             // 0..31  (batch row)
    const int xq   = thr & 7;              // 16 floats each

    for (int t = 0; t < 512; ++t) {
        // ---- stage B-h: h slice [32][256] hi+lo (proven layout) ----
        const __nv_bfloat16* hsrc0 = g_hh[t & 1] + ks * 256;
        const __nv_bfloat16* hsrc1 = g_hl[t & 1] + ks * 256;
#pragma unroll
        for (int ii = 0; ii < 8; ++ii) {
            int idx  = ii * 256 + thr;
            int hsel = idx >> 10;
            int rq   = idx & 1023;
            int row  = rq >> 5, q = rq & 31;
            const __nv_bfloat16* src = (hsel ? hsrc1 : hsrc0) + row * 1024;
            uint4 v = ldcg4((const uint4*)src + q);
            *(uint4*)(sm + hsel * 16896 + row * 528 + q * 16) = v;
        }
        // ---- stage B-x: emb gather [32][128] fp32 -> hi/lo bf16 ----
        {
            int tokx = g_tokens[xrow * 512 + t];
            const float* xs = emb + (size_t)tokx * 512 + ks * 128 + xq * 16;
            uint32_t hiw[8], low[8];
#pragma unroll
            for (int p = 0; p < 4; ++p) {
                float4 v = __ldg((const float4*)(xs + p * 4));
                float r0, r1, r2, r3;
                unsigned short h0 = bf_hi(v.x, r0), h1 = bf_hi(v.y, r1);
                unsigned short h2 = bf_hi(v.z, r2), h3 = bf_hi(v.w, r3);
                hiw[p * 2]     = (uint32_t)h0 | ((uint32_t)h1 << 16);
                hiw[p * 2 + 1] = (uint32_t)h2 | ((uint32_t)h3 << 16);
                low[p * 2]     = (uint32_t)bf_of(r0) | ((uint32_t)bf_of(r1) << 16);
                low[p * 2 + 1] = (uint32_t)bf_of(r2) | ((uint32_t)bf_of(r3) << 16);
            }
            char* xd = sm + SM_XOFF + xrow * 272 + xq * 32;
            *(uint4*)xd        = make_uint4(hiw[0], hiw[1], hiw[2], hiw[3]);
            *(uint4*)(xd + 16) = make_uint4(hiw[4], hiw[5], hiw[6], hiw[7]);
            *(uint4*)(xd + SM_XHALF)      = make_uint4(low[0], low[1], low[2], low[3]);
            *(uint4*)(xd + SM_XHALF + 16) = make_uint4(low[4], low[5], low[6], low[7]);
        }
        __syncthreads();

        // ---- mma mainloop: 24 k-chunks (16 h + 8 x), fully unrolled ----
        float d[4][4];
#pragma unroll
        for (int nf = 0; nf < 4; ++nf)
#pragma unroll
            for (int i = 0; i < 4; ++i) d[nf][i] = 0.f;

        // A-hi depth-2 register prefetch; chunks 0..7 streamed (ldcg),
        // chunks 8..23 L1-resident (ldg).
        uint4 ahP0 = ldcg4(&g_pkA_hi[abase]);
        uint4 ahP1 = ldcg4(&g_pkA_hi[abase + 32]);
#pragma unroll
        for (int c = 0; c < 24; ++c) {
            uint4 ah = ahP0;
            ahP0 = ahP1;
            if (c + 2 < 24) {
                if (c + 2 < 8) ahP1 = ldcg4(&g_pkA_hi[abase + (c + 2) * 32]);
                else           ahP1 = __ldg(&g_pkA_hi[abase + (c + 2) * 32]);
            }
            uint4 al = *(const uint4*)(aloPtr + c * 512);

            uint32_t a0, a1, loOff;
            if (c < 16) {
                a0 = sbB + nrowoff * 528 + c * 32 + koff;
                a1 = a0 + 16 * 528;
                loOff = 16896;
            } else {
                a0 = sbX + nrowoff * 272 + (c - 16) * 32 + koff;
                a1 = a0 + 16 * 272;
                loOff = SM_XHALF;
            }
            uint32_t bh[8], bl[8];
            LDSM4(bh[0], bh[1], bh[2], bh[3], a0);
            LDSM4(bh[4], bh[5], bh[6], bh[7], a1);
            LDSM4(bl[0], bl[1], bl[2], bl[3], a0 + loOff);
            LDSM4(bl[4], bl[5], bl[6], bl[7], a1 + loOff);
#pragma unroll
            for (int nf = 0; nf < 4; ++nf) {
                MMA_BF16(d[nf], ah.x, ah.y, ah.z, ah.w, bh[nf * 2], bh[nf * 2 + 1]);
                MMA_BF16(d[nf], ah.x, ah.y, ah.z, ah.w, bl[nf * 2], bl[nf * 2 + 1]);
                MMA_BF16(d[nf], al.x, al.y, al.z, al.w, bh[nf * 2], bh[nf * 2 + 1]);
            }
        }

        // ---- store partials (proven scattered stores) ----
#pragma unroll
        for (int nf = 0; nf < 4; ++nf) {
            int bcol = nf * 8 + ((lane & 3) << 1);
            g_part[ks][bcol][Mg0]     = d[nf][0];
            g_part[ks][bcol + 1][Mg0] = d[nf][1];
            g_part[ks][bcol][Mg8]     = d[nf][2];
            g_part[ks][bcol + 1][Mg8] = d[nf][3];
        }
        grid_barrier();

        // ---- phase 2: reduce + gates ----
        {
            float z0 = biasr[0], z1 = biasr[1], z2 = biasr[2], z3 = biasr[3];
#pragma unroll
            for (int kr = 0; kr < 4; ++kr) {
                z0 += __ldcg(&g_part[kr][b_idx][u_idx]);
                z1 += __ldcg(&g_part[kr][b_idx][u_idx + 1024]);
                z2 += __ldcg(&g_part[kr][b_idx][u_idx + 2048]);
                z3 += __ldcg(&g_part[kr][b_idx][u_idx + 3072]);
            }
            float gi = tanhf(z0);
            float gf = tanhf(z1);
            float gg = tanhf(z2);
            float go = tanhf(z3);
            float cn = fmaf(gf, creg, gi * gg);
            float hn = go * tanhf(cn);
            if (tokv != 0) { creg = cn; hreg = hn; }
            float rem;
            unsigned short hb = bf_hi(hreg, rem);
            *(unsigned short*)&g_hh[(t + 1) & 1][tid] = hb;
            *(unsigned short*)&g_hl[(t + 1) & 1][tid] = bf_of(rem);

            if (t + 1 < 512) tokv = g_tokens[b_idx * 512 + t + 1];
        }
        grid_barrier();
    }

    out[b_idx * 1024 + u_idx]         = hreg;
    out[32768 + b_idx * 1024 + u_idx] = hreg;
    out[65536 + b_idx * 1024 + u_idx] = creg;
}

// ---------------- launch ----------------
extern "C" void kernel_launch(void* const* d_in, const int* in_sizes, int n_in,
                              void* d_out, int out_size)
{
    const int*   tokens_raw = (const int*)  d_in[0];
    const float* emb        = (const float*)d_in[1];
    const float* W          = (const float*)d_in[2];
    const float* U          = (const float*)d_in[3];
    const float* bias       = (const float*)d_in[4];
    float*       out        = (float*)d_out;
    (void)in_sizes; (void)n_in; (void)out_size;

    cudaFuncSetAttribute(lstm_kernel,
                         cudaFuncAttributeMaxDynamicSharedMemorySize, SM_TOTAL);

    pack_UW_kernel<<<3072, 256>>>(U, W);
    lstm_kernel<<<NCTA, 256, SM_TOTAL>>>(tokens_raw, emb, bias, out);
}